// round 14
// baseline (speedup 1.0000x reference)
#include <cuda_runtime.h>
#include <cuda_fp16.h>
#include <math.h>
#include <stdint.h>
#include <cstdint>

#define NH   16
#define NKV  4
#define HD   128
#define BB   2
#define SEQ  2048
#define HID  2048
#define MROWS (BB*SEQ)
#define NQKV 3072

// scale folded into Q: (1/sqrt(128)) * log2(e)
#define QSCL 0.1275174337f

// ---------------- device scratch ----------------
__device__ __half g_hX  [MROWS*HID];
__device__ __half g_Wqkv[NQKV*HID];        // Wq | Wk | Wv rows
__device__ __half g_Wo  [HID*NH*HD];
__device__ __half g_Q   [BB*NH*SEQ*HD];
__device__ __half g_K   [BB*NKV*SEQ*HD];
__device__ __half g_V   [BB*NKV*SEQ*HD];
__device__ __half g_attn[MROWS*NH*HD];
__device__ float  g_cos[SEQ*64];
__device__ float  g_sin[SEQ*64];

// ---------------- cp.async helpers ----------------
__device__ __forceinline__ void cp_async16(void* smem, const void* gmem)
{
    unsigned s = (unsigned)__cvta_generic_to_shared(smem);
    asm volatile("cp.async.cg.shared.global [%0], [%1], 16;\n" :: "r"(s), "l"(gmem));
}
__device__ __forceinline__ void cp_commit() { asm volatile("cp.async.commit_group;\n"); }
template<int N> __device__ __forceinline__ void cp_wait()
{
    asm volatile("cp.async.wait_group %0;\n" :: "n"(N));
}

// ---------------- mma / ldmatrix primitives ----------------
__device__ __forceinline__ uint32_t smaddr(const void* p)
{
    return (uint32_t)__cvta_generic_to_shared(p);
}
__device__ __forceinline__ void ldsm_x4(uint32_t a, uint32_t& r0, uint32_t& r1,
                                        uint32_t& r2, uint32_t& r3)
{
    asm volatile("ldmatrix.sync.aligned.m8n8.x4.shared.b16 {%0,%1,%2,%3}, [%4];"
                 : "=r"(r0), "=r"(r1), "=r"(r2), "=r"(r3) : "r"(a));
}
__device__ __forceinline__ void ldsm_x4_t(uint32_t a, uint32_t& r0, uint32_t& r1,
                                          uint32_t& r2, uint32_t& r3)
{
    asm volatile("ldmatrix.sync.aligned.m8n8.x4.trans.shared.b16 {%0,%1,%2,%3}, [%4];"
                 : "=r"(r0), "=r"(r1), "=r"(r2), "=r"(r3) : "r"(a));
}
__device__ __forceinline__ void mma16816(float* c, const uint32_t* a, uint32_t b0, uint32_t b1)
{
    asm volatile("mma.sync.aligned.m16n8k16.row.col.f32.f16.f16.f32 "
                 "{%0,%1,%2,%3}, {%4,%5,%6,%7}, {%8,%9}, {%0,%1,%2,%3};"
                 : "+f"(c[0]), "+f"(c[1]), "+f"(c[2]), "+f"(c[3])
                 : "r"(a[0]), "r"(a[1]), "r"(a[2]), "r"(a[3]), "r"(b0), "r"(b1));
}
__device__ __forceinline__ uint32_t h2pack(float x, float y)
{
    __half2 h = __floats2half2_rn(x, y);
    return *(uint32_t*)&h;
}

// ---------------- split conversions ----------------
// convA: hX batch0 | Wq | Wk | Wv  (+ rope table tail)   [critical for chain b0]
#define CA0 1048576L
#define CA1 (CA0 + 1048576L)
#define CA2 (CA1 + 524288L)
#define CA3 (CA2 + 524288L)        // 3145728 float4
#define TAB_BLOCKS 512
#define CONVA_BLOCKS (CA3 / 256 + TAB_BLOCKS)

__global__ void convA(const float4* __restrict__ hX, const float4* __restrict__ Wq,
                      const float4* __restrict__ Wk, const float4* __restrict__ Wv)
{
    long i = (long)blockIdx.x * 256 + threadIdx.x;
    if (i >= CA3) {
        long t = i - CA3;                     // 0..131071
        int s = (int)(t / 64), k = (int)(t % 64);
        double inv = pow(10000.0, -(double)k / 64.0);
        double ang = (double)s * inv;
        double sn, cs;
        sincos(ang, &sn, &cs);
        g_cos[t] = (float)cs;
        g_sin[t] = (float)sn;
        return;
    }
    const float4* src; __half* dst; long off;
    if (i < CA0)      { src = hX; dst = g_hX;   off = i; }
    else if (i < CA1) { src = Wq; dst = g_Wqkv; off = i - CA0; }
    else if (i < CA2) { src = Wk; dst = g_Wqkv + (size_t)2048*HID; off = i - CA1; }
    else              { src = Wv; dst = g_Wqkv + (size_t)2560*HID; off = i - CA2; }
    float4 v = src[off];
    __half2* d = (__half2*)(dst + off * 4);
    d[0] = __floats2half2_rn(v.x, v.y);
    d[1] = __floats2half2_rn(v.z, v.w);
}

// convB: hX batch1 | Wo   [needed by chain b1 start, and Wo by both oproj]
#define CB0 1048576L
#define CB1 (CB0 + 1048576L)       // 2097152 float4
#define CONVB_BLOCKS (CB1 / 256)

__global__ void convB(const float4* __restrict__ hXb1, const float4* __restrict__ Wo)
{
    long i = (long)blockIdx.x * 256 + threadIdx.x;
    const float4* src; __half* dst; long off;
    if (i < CB0) { src = hXb1; dst = g_hX + (size_t)SEQ*HID; off = i; }
    else         { src = Wo;   dst = g_Wo;                   off = i - CB0; }
    float4 v = src[off];
    __half2* d = (__half2*)(dst + off * 4);
    d[0] = __floats2half2_rn(v.x, v.y);
    d[1] = __floats2half2_rn(v.z, v.w);
}

// ======== Raw-mma TN GEMM, CTA 128x128, warp tile 64x32, 2 CTAs/SM ========
// mode 0: plain fp32 C; mode 1: fused QKV epilogue, head = blockIdx.x
//   (head 0-15 Q rope*QSCL, 16-19 K rope, 20-23 V convert); batch passed explicitly.
#define GBM 128
#define GBN 128
#define GBK 64
#define GST 72
#define GNSTG 3
#define GEMM_SMEM (GNSTG*(GBM+GBN)*GST*2)    // 110592 B
#define EST 132

__global__ void __launch_bounds__(256, 2) gemm_tn(const __half* __restrict__ A,
                                                  const __half* __restrict__ Bm,
                                                  float* __restrict__ C,
                                                  int M, int N, int K, int mode, int batch)
{
    extern __shared__ __align__(16) __half sm[];
    const int tid = threadIdx.x;
    const int w = tid >> 5, l = tid & 31;
    const int wm = w >> 2, wn = w & 3;
    const int m0 = blockIdx.y * GBM, n0 = blockIdx.x * GBN;
    const int NT = K / GBK;
    const int stageH = (GBM + GBN) * GST;

    auto loadStage = [&](int t) {
        __half* sA = sm + (size_t)(t % GNSTG) * stageH;
        __half* sB = sA + GBM * GST;
        const __half* Ag = A + (size_t)m0 * K + t * GBK;
        const __half* Bg = Bm + (size_t)n0 * K + t * GBK;
#pragma unroll
        for (int i = 0; i < 4; i++) {
            int u = tid + i * 256;
            int r = u >> 3, c = (u & 7) * 8;
            cp_async16(sA + r * GST + c, Ag + (size_t)r * K + c);
        }
#pragma unroll
        for (int i = 0; i < 4; i++) {
            int u = tid + i * 256;
            int r = u >> 3, c = (u & 7) * 8;
            cp_async16(sB + r * GST + c, Bg + (size_t)r * K + c);
        }
        cp_commit();
    };

    loadStage(0); loadStage(1);

    float acc[4][4][4];
#pragma unroll
    for (int mi = 0; mi < 4; mi++)
#pragma unroll
        for (int nj = 0; nj < 4; nj++)
#pragma unroll
            for (int e = 0; e < 4; e++) acc[mi][nj][e] = 0.0f;

    const int arow_l = (l & 15);
    const int acoff  = (l >> 4) * 8;
    const int krow   = (l & 7) + ((l >> 4) << 3);
    const int kcol   = ((l >> 3) & 1) * 8;

    for (int t = 0; t < NT; t++) {
        if (t < NT - 1) cp_wait<1>(); else cp_wait<0>();
        __syncthreads();
        if (t + 2 < NT) loadStage(t + 2);

        const __half* sA = sm + (size_t)(t % GNSTG) * stageH;
        const __half* sB = sA + GBM * GST;

#pragma unroll
        for (int dc = 0; dc < 4; dc++) {
            uint32_t a[4][4];
#pragma unroll
            for (int mi = 0; mi < 4; mi++)
                ldsm_x4(smaddr(sA + (wm * 64 + mi * 16 + arow_l) * GST + dc * 16 + acoff),
                        a[mi][0], a[mi][1], a[mi][2], a[mi][3]);
#pragma unroll
            for (int np = 0; np < 2; np++) {
                uint32_t b0, b1, b2, b3;
                ldsm_x4(smaddr(sB + (wn * 32 + np * 16 + krow) * GST + dc * 16 + kcol),
                        b0, b1, b2, b3);
#pragma unroll
                for (int mi = 0; mi < 4; mi++) {
                    mma16816(acc[mi][2 * np],     a[mi], b0, b1);
                    mma16816(acc[mi][2 * np + 1], a[mi], b2, b3);
                }
            }
        }
    }

    if (mode == 0) {
#pragma unroll
        for (int mi = 0; mi < 4; mi++) {
            int row = m0 + wm * 64 + mi * 16 + (l >> 2);
            float* C0 = C + (size_t)row * N + n0 + wn * 32;
            float* C1 = C0 + (size_t)8 * N;
#pragma unroll
            for (int nj = 0; nj < 4; nj++) {
                int col = nj * 8 + (l & 3) * 2;
                *(float2*)(C0 + col) = make_float2(acc[mi][nj][0], acc[mi][nj][1]);
                *(float2*)(C1 + col) = make_float2(acc[mi][nj][2], acc[mi][nj][3]);
            }
        }
        return;
    }

    // fused QKV epilogue (one head per CTA): stage fp32 tile through smem
    __syncthreads();
    float* sC = (float*)sm;
#pragma unroll
    for (int mi = 0; mi < 4; mi++) {
        int r0 = wm * 64 + mi * 16 + (l >> 2);
#pragma unroll
        for (int nj = 0; nj < 4; nj++) {
            int c0 = wn * 32 + nj * 8 + (l & 3) * 2;
            sC[r0 * EST + c0]           = acc[mi][nj][0];
            sC[r0 * EST + c0 + 1]       = acc[mi][nj][1];
            sC[(r0 + 8) * EST + c0]     = acc[mi][nj][2];
            sC[(r0 + 8) * EST + c0 + 1] = acc[mi][nj][3];
        }
    }
    __syncthreads();

    const int sbase = m0;                      // A is per-batch, m0 in [0, SEQ)
    const int bx = blockIdx.x;                 // head idx: 0-15 Q, 16-19 K, 20-23 V

    bool do_rope;
    float scl;
    __half* dst;
    if (bx < 16) {
        do_rope = true; scl = QSCL;
        dst = g_Q + ((size_t)(batch * NH + bx) * SEQ) * HD;
    } else if (bx < 20) {
        do_rope = true; scl = 1.0f;
        dst = g_K + ((size_t)(batch * NKV + (bx - 16)) * SEQ) * HD;
    } else {
        do_rope = false; scl = 1.0f;
        dst = g_V + ((size_t)(batch * NKV + (bx - 20)) * SEQ) * HD;
    }

    if (do_rope) {
#pragma unroll
        for (int i = 0; i < 32; i++) {
            int u = tid + i * 256;
            int r = u >> 6, c = u & 63;
            float x1 = sC[r * EST + c], x2 = sC[r * EST + c + 64];
            int s = sbase + r;
            float cs = g_cos[s * 64 + c], sn = g_sin[s * 64 + c];
            dst[(size_t)s * HD + c]      = __float2half((x1 * cs - x2 * sn) * scl);
            dst[(size_t)s * HD + c + 64] = __float2half((x2 * cs + x1 * sn) * scl);
        }
    } else {
#pragma unroll
        for (int i = 0; i < 32; i++) {
            int u = tid + i * 256;
            int r = u >> 6, d2 = (u & 63) * 2;
            int s = sbase + r;
            *(__half2*)(dst + (size_t)s * HD + d2) =
                __floats2half2_rn(sC[r * EST + d2], sC[r * EST + d2 + 1]);
        }
    }
}

// ---------------- FA2 flash attention: 2 k-tiles per softmax (R12-proven) ----------------
#define TQA 128
#define TKA 64
#define SQL 136
#define NSTG 4
#define ATTN_SMEM ((TQA*SQL + 2*NSTG*TKA*SQL)*2)

__global__ void __launch_bounds__(256) attn_kernel(int batch)
{
    extern __shared__ __align__(16) char smem_raw[];
    __half* sQ = (__half*)smem_raw;
    __half* sK = sQ + TQA * SQL;
    __half* sV = sK + NSTG * TKA * SQL;

    const int tid = threadIdx.x;
    const int w = tid >> 5, l = tid & 31;
    const int q0 = blockIdx.x * TQA;
    const int h = blockIdx.y;
    const int b = batch;
    const int kvh = h / (NH / NKV);

    const __half* Qg = g_Q + ((size_t)(b * NH + h) * SEQ + q0) * HD;
    const __half* Kg = g_K + ((size_t)(b * NKV + kvh) * SEQ) * HD;
    const __half* Vg = g_V + ((size_t)(b * NKV + kvh) * SEQ) * HD;
    const int NT2 = SEQ / (2 * TKA);

#pragma unroll
    for (int i = 0; i < 8; i++) {
        int u = tid + i * 256;
        int r = u >> 4, c = (u & 15) * 8;
        cp_async16(sQ + r * SQL + c, Qg + r * HD + c);
    }

    auto loadKV = [&](int t) {
        const __half* ks = Kg + (size_t)t * TKA * HD;
        const __half* vs = Vg + (size_t)t * TKA * HD;
        __half* kd = sK + (size_t)(t & (NSTG - 1)) * TKA * SQL;
        __half* vd = sV + (size_t)(t & (NSTG - 1)) * TKA * SQL;
#pragma unroll
        for (int i = 0; i < 4; i++) {
            int u = tid + i * 256;
            int r = u >> 4, c = (u & 15) * 8;
            cp_async16(kd + r * SQL + c, ks + r * HD + c);
            cp_async16(vd + r * SQL + c, vs + r * HD + c);
        }
        cp_commit();
    };
    loadKV(0);                   // group also carries Q
    loadKV(1); loadKV(2); loadKV(3);

    cp_wait<2>();
    __syncthreads();

    uint32_t qa[8][4];
    {
        int qrow = w * 16 + (l & 15);
        int coff = (l >> 4) * 8;
#pragma unroll
        for (int dc = 0; dc < 8; dc++)
            ldsm_x4(smaddr(sQ + qrow * SQL + dc * 16 + coff),
                    qa[dc][0], qa[dc][1], qa[dc][2], qa[dc][3]);
    }

    float o[16][4];
#pragma unroll
    for (int j = 0; j < 16; j++)
#pragma unroll
        for (int i = 0; i < 4; i++) o[j][i] = 0.0f;
    float m0 = -1e30f, m1 = -1e30f, l0 = 0.0f, l1 = 0.0f;

    const int krow = (l & 7) + ((l >> 4) << 3);
    const int kcol = ((l >> 3) & 1) * 8;
    const int vrow = (l & 7) + (((l >> 3) & 1) << 3);
    const int vcol = (l >> 4) * 8;

    for (int jt = 0; jt < NT2; jt++) {
        if (jt < NT2 - 1) cp_wait<2>(); else cp_wait<0>();
        __syncthreads();

        const int tA = 2 * jt, tB = 2 * jt + 1;
        const __half* KtA = sK + (size_t)(tA & (NSTG - 1)) * TKA * SQL;
        const __half* KtB = sK + (size_t)(tB & (NSTG - 1)) * TKA * SQL;
        const __half* VtA = sV + (size_t)(tA & (NSTG - 1)) * TKA * SQL;
        const __half* VtB = sV + (size_t)(tB & (NSTG - 1)) * TKA * SQL;

        float s[16][4];
#pragma unroll
        for (int j = 0; j < 16; j++)
#pragma unroll
            for (int i = 0; i < 4; i++) s[j][i] = 0.0f;
#pragma unroll
        for (int dc = 0; dc < 8; dc++) {
#pragma unroll
            for (int np = 0; np < 4; np++) {
                uint32_t b0, b1, b2, b3;
                ldsm_x4(smaddr(KtA + (np * 16 + krow) * SQL + dc * 16 + kcol),
                        b0, b1, b2, b3);
                mma16816(s[2 * np],     qa[dc], b0, b1);
                mma16816(s[2 * np + 1], qa[dc], b2, b3);
            }
#pragma unroll
            for (int np = 0; np < 4; np++) {
                uint32_t b0, b1, b2, b3;
                ldsm_x4(smaddr(KtB + (np * 16 + krow) * SQL + dc * 16 + kcol),
                        b0, b1, b2, b3);
                mma16816(s[8 + 2 * np],     qa[dc], b0, b1);
                mma16816(s[8 + 2 * np + 1], qa[dc], b2, b3);
            }
        }

        float mx0 = -1e30f, mx1 = -1e30f;
#pragma unroll
        for (int j = 0; j < 16; j++) {
            mx0 = fmaxf(mx0, fmaxf(s[j][0], s[j][1]));
            mx1 = fmaxf(mx1, fmaxf(s[j][2], s[j][3]));
        }
        mx0 = fmaxf(mx0, __shfl_xor_sync(0xffffffffu, mx0, 1));
        mx0 = fmaxf(mx0, __shfl_xor_sync(0xffffffffu, mx0, 2));
        mx1 = fmaxf(mx1, __shfl_xor_sync(0xffffffffu, mx1, 1));
        mx1 = fmaxf(mx1, __shfl_xor_sync(0xffffffffu, mx1, 2));
        float mn0 = fmaxf(m0, mx0), mn1 = fmaxf(m1, mx1);

        float f0 = 1.0f, f1 = 1.0f;
        bool upd = (mn0 > m0) || (mn1 > m1);
        if (__any_sync(0xffffffffu, upd)) {
            f0 = exp2f(m0 - mn0); f1 = exp2f(m1 - mn1);
            m0 = mn0; m1 = mn1;
#pragma unroll
            for (int j = 0; j < 16; j++) {
                o[j][0] *= f0; o[j][1] *= f0;
                o[j][2] *= f1; o[j][3] *= f1;
            }
        }

        float sum0 = 0.0f, sum1 = 0.0f;
#pragma unroll
        for (int j = 0; j < 16; j++) {
            s[j][0] = exp2f(s[j][0] - mn0);
            s[j][1] = exp2f(s[j][1] - mn0);
            s[j][2] = exp2f(s[j][2] - mn1);
            s[j][3] = exp2f(s[j][3] - mn1);
            sum0 += s[j][0] + s[j][1];
            sum1 += s[j][2] + s[j][3];
        }
        sum0 += __shfl_xor_sync(0xffffffffu, sum0, 1);
        sum0 += __shfl_xor_sync(0xffffffffu, sum0, 2);
        sum1 += __shfl_xor_sync(0xffffffffu, sum1, 1);
        sum1 += __shfl_xor_sync(0xffffffffu, sum1, 2);
        l0 = l0 * f0 + sum0;
        l1 = l1 * f1 + sum1;

#pragma unroll
        for (int t = 0; t < 4; t++) {
            uint32_t pa[4];
            pa[0] = h2pack(s[2 * t][0],     s[2 * t][1]);
            pa[1] = h2pack(s[2 * t][2],     s[2 * t][3]);
            pa[2] = h2pack(s[2 * t + 1][0], s[2 * t + 1][1]);
            pa[3] = h2pack(s[2 * t + 1][2], s[2 * t + 1][3]);
#pragma unroll
            for (int npp = 0; npp < 8; npp++) {
                uint32_t b0, b1, b2, b3;
                ldsm_x4_t(smaddr(VtA + (t * 16 + vrow) * SQL + npp * 16 + vcol),
                          b0, b1, b2, b3);
                mma16816(o[2 * npp],     pa, b0, b1);
                mma16816(o[2 * npp + 1], pa, b2, b3);
            }
        }
#pragma unroll
        for (int t = 0; t < 4; t++) {
            uint32_t pa[4];
            pa[0] = h2pack(s[8 + 2 * t][0],     s[8 + 2 * t][1]);
            pa[1] = h2pack(s[8 + 2 * t][2],     s[8 + 2 * t][3]);
            pa[2] = h2pack(s[8 + 2 * t + 1][0], s[8 + 2 * t + 1][1]);
            pa[3] = h2pack(s[8 + 2 * t + 1][2], s[8 + 2 * t + 1][3]);
#pragma unroll
            for (int npp = 0; npp < 8; npp++) {
                uint32_t b0, b1, b2, b3;
                ldsm_x4_t(smaddr(VtB + (t * 16 + vrow) * SQL + npp * 16 + vcol),
                          b0, b1, b2, b3);
                mma16816(o[2 * npp],     pa, b0, b1);
                mma16816(o[2 * npp + 1], pa, b2, b3);
            }
        }

        __syncthreads();
        if (tA + 4 < 2 * NT2) { loadKV(tA + 4); loadKV(tB + 4); }
    }

    float inv0 = 1.0f / l0, inv1 = 1.0f / l1;
    int grow = b * SEQ + q0 + w * 16 + (l >> 2);
    __half* O0 = g_attn + (size_t)grow * (NH * HD) + h * HD;
    __half* O1 = O0 + (size_t)8 * (NH * HD);
#pragma unroll
    for (int j = 0; j < 16; j++) {
        int col = j * 8 + 2 * (l & 3);
        *(__half2*)(O0 + col) = __floats2half2_rn(o[j][0] * inv0, o[j][1] * inv0);
        *(__half2*)(O1 + col) = __floats2half2_rn(o[j][2] * inv1, o[j][3] * inv1);
    }
}

// ---------------- launch: split conversions + two per-batch chains ----------------
extern "C" void kernel_launch(void* const* d_in, const int* in_sizes, int n_in,
                              void* d_out, int out_size)
{
    const float* hidden = (const float*)d_in[0];
    const float* Wq = (const float*)d_in[1];
    const float* Wk = (const float*)d_in[2];
    const float* Wv = (const float*)d_in[3];
    const float* Wo = (const float*)d_in[4];
    float* out = (float*)d_out;

    static cudaStream_t s_aux = nullptr;
    static cudaEvent_t  s_evA = nullptr, s_evW = nullptr, s_evB = nullptr;
    if (s_aux == nullptr) {
        cudaStreamCreateWithFlags(&s_aux, cudaStreamNonBlocking);
        cudaEventCreateWithFlags(&s_evA, cudaEventDisableTiming);
        cudaEventCreateWithFlags(&s_evW, cudaEventDisableTiming);
        cudaEventCreateWithFlags(&s_evB, cudaEventDisableTiming);
    }

    cudaFuncSetAttribute(attn_kernel, cudaFuncAttributeMaxDynamicSharedMemorySize, ATTN_SMEM);
    cudaFuncSetAttribute(gemm_tn, cudaFuncAttributeMaxDynamicSharedMemorySize, GEMM_SMEM);

    __half *p_hX, *p_Wqkv, *p_Wo, *p_attn;
    cudaGetSymbolAddress((void**)&p_hX,   g_hX);
    cudaGetSymbolAddress((void**)&p_Wqkv, g_Wqkv);
    cudaGetSymbolAddress((void**)&p_Wo,   g_Wo);
    cudaGetSymbolAddress((void**)&p_attn, g_attn);

    const int T = 256;

    // convA (critical for chain b0): hX[b0] + Wqkv + rope table   [main]
    convA<<<CONVA_BLOCKS, T>>>((const float4*)hidden, (const float4*)Wq,
                               (const float4*)Wk, (const float4*)Wv);
    cudaEventRecord(s_evA, 0);
    cudaStreamWaitEvent(s_aux, s_evA, 0);

    // convB: hX[b1] + Wo   [aux, overlaps chain b0's QKV gemm]
    convB<<<CONVB_BLOCKS, T, 0, s_aux>>>(
        (const float4*)(hidden + (size_t)SEQ*HID), (const float4*)Wo);
    cudaEventRecord(s_evW, s_aux);

    // chain b=0 on main stream
    gemm_tn<<<dim3(NQKV/GBN, SEQ/GBM), T, GEMM_SMEM>>>(
        p_hX, p_Wqkv, (float*)nullptr, SEQ, NQKV, HID, 1, 0);
    attn_kernel<<<dim3(SEQ/TQA, NH), T, ATTN_SMEM>>>(0);
    cudaStreamWaitEvent(0, s_evW, 0);          // Wo converted (always ready by now)
    gemm_tn<<<dim3(HID/GBN, SEQ/GBM), T, GEMM_SMEM>>>(
        p_attn, p_Wo, out, SEQ, HID, NH*HD, 0, 0);

    // chain b=1 on aux stream
    gemm_tn<<<dim3(NQKV/GBN, SEQ/GBM), T, GEMM_SMEM, s_aux>>>(
        p_hX + (size_t)SEQ*HID, p_Wqkv, (float*)nullptr, SEQ, NQKV, HID, 1, 1);
    attn_kernel<<<dim3(SEQ/TQA, NH), T, ATTN_SMEM, s_aux>>>(1);
    gemm_tn<<<dim3(HID/GBN, SEQ/GBM), T, GEMM_SMEM, s_aux>>>(
        p_attn + (size_t)SEQ*NH*HD, p_Wo, out + (size_t)SEQ*HID, SEQ, HID, NH*HD, 0, 1);

    // join
    cudaEventRecord(s_evB, s_aux);
    cudaStreamWaitEvent(0, s_evB, 0);
}

// round 15
// speedup vs baseline: 1.0084x; 1.0084x over previous
#include <cuda_runtime.h>
#include <cuda_fp16.h>
#include <math.h>
#include <stdint.h>
#include <cstdint>

#define NH   16
#define NKV  4
#define HD   128
#define BB   2
#define SEQ  2048
#define HID  2048
#define MROWS (BB*SEQ)
#define NQKV 3072

// scale folded into Q: (1/sqrt(128)) * log2(e)
#define QSCL 0.1275174337f

// ---------------- device scratch ----------------
__device__ __half g_hX  [MROWS*HID];
__device__ __half g_Wqkv[NQKV*HID];        // Wq | Wk | Wv rows
__device__ __half g_Wo  [HID*NH*HD];
__device__ __half g_Q   [BB*NH*SEQ*HD];
__device__ __half g_K   [BB*NKV*SEQ*HD];
__device__ __half g_V   [BB*NKV*SEQ*HD];
__device__ __half g_attn[MROWS*NH*HD];
__device__ float  g_cos[SEQ*64];
__device__ float  g_sin[SEQ*64];

// ---------------- cp.async helpers ----------------
__device__ __forceinline__ void cp_async16(void* smem, const void* gmem)
{
    unsigned s = (unsigned)__cvta_generic_to_shared(smem);
    asm volatile("cp.async.cg.shared.global [%0], [%1], 16;\n" :: "r"(s), "l"(gmem));
}
__device__ __forceinline__ void cp_commit() { asm volatile("cp.async.commit_group;\n"); }
template<int N> __device__ __forceinline__ void cp_wait()
{
    asm volatile("cp.async.wait_group %0;\n" :: "n"(N));
}

// ---------------- mma / ldmatrix primitives ----------------
__device__ __forceinline__ uint32_t smaddr(const void* p)
{
    return (uint32_t)__cvta_generic_to_shared(p);
}
__device__ __forceinline__ void ldsm_x4(uint32_t a, uint32_t& r0, uint32_t& r1,
                                        uint32_t& r2, uint32_t& r3)
{
    asm volatile("ldmatrix.sync.aligned.m8n8.x4.shared.b16 {%0,%1,%2,%3}, [%4];"
                 : "=r"(r0), "=r"(r1), "=r"(r2), "=r"(r3) : "r"(a));
}
__device__ __forceinline__ void ldsm_x4_t(uint32_t a, uint32_t& r0, uint32_t& r1,
                                          uint32_t& r2, uint32_t& r3)
{
    asm volatile("ldmatrix.sync.aligned.m8n8.x4.trans.shared.b16 {%0,%1,%2,%3}, [%4];"
                 : "=r"(r0), "=r"(r1), "=r"(r2), "=r"(r3) : "r"(a));
}
__device__ __forceinline__ void mma16816(float* c, const uint32_t* a, uint32_t b0, uint32_t b1)
{
    asm volatile("mma.sync.aligned.m16n8k16.row.col.f32.f16.f16.f32 "
                 "{%0,%1,%2,%3}, {%4,%5,%6,%7}, {%8,%9}, {%0,%1,%2,%3};"
                 : "+f"(c[0]), "+f"(c[1]), "+f"(c[2]), "+f"(c[3])
                 : "r"(a[0]), "r"(a[1]), "r"(a[2]), "r"(a[3]), "r"(b0), "r"(b1));
}
__device__ __forceinline__ uint32_t h2pack(float x, float y)
{
    __half2 h = __floats2half2_rn(x, y);
    return *(uint32_t*)&h;
}

// ---------------- split conversions ----------------
#define CA0 1048576L
#define CA1 (CA0 + 1048576L)
#define CA2 (CA1 + 524288L)
#define CA3 (CA2 + 524288L)
#define TAB_BLOCKS 512
#define CONVA_BLOCKS (CA3 / 256 + TAB_BLOCKS)

__global__ void convA(const float4* __restrict__ hX, const float4* __restrict__ Wq,
                      const float4* __restrict__ Wk, const float4* __restrict__ Wv)
{
    long i = (long)blockIdx.x * 256 + threadIdx.x;
    if (i >= CA3) {
        long t = i - CA3;
        int s = (int)(t / 64), k = (int)(t % 64);
        double inv = pow(10000.0, -(double)k / 64.0);
        double ang = (double)s * inv;
        double sn, cs;
        sincos(ang, &sn, &cs);
        g_cos[t] = (float)cs;
        g_sin[t] = (float)sn;
        return;
    }
    const float4* src; __half* dst; long off;
    if (i < CA0)      { src = hX; dst = g_hX;   off = i; }
    else if (i < CA1) { src = Wq; dst = g_Wqkv; off = i - CA0; }
    else if (i < CA2) { src = Wk; dst = g_Wqkv + (size_t)2048*HID; off = i - CA1; }
    else              { src = Wv; dst = g_Wqkv + (size_t)2560*HID; off = i - CA2; }
    float4 v = src[off];
    __half2* d = (__half2*)(dst + off * 4);
    d[0] = __floats2half2_rn(v.x, v.y);
    d[1] = __floats2half2_rn(v.z, v.w);
}

#define CB0 1048576L
#define CB1 (CB0 + 1048576L)
#define CONVB_BLOCKS (CB1 / 256)

__global__ void convB(const float4* __restrict__ hXb1, const float4* __restrict__ Wo)
{
    long i = (long)blockIdx.x * 256 + threadIdx.x;
    const float4* src; __half* dst; long off;
    if (i < CB0) { src = hXb1; dst = g_hX + (size_t)SEQ*HID; off = i; }
    else         { src = Wo;   dst = g_Wo;                   off = i - CB0; }
    float4 v = src[off];
    __half2* d = (__half2*)(dst + off * 4);
    d[0] = __floats2half2_rn(v.x, v.y);
    d[1] = __floats2half2_rn(v.z, v.w);
}

// ======== Raw-mma TN GEMM, CTA 128x128, warp tile 64x32, 2 CTAs/SM ========
#define GBM 128
#define GBN 128
#define GBK 64
#define GST 72
#define GNSTG 3
#define GEMM_SMEM (GNSTG*(GBM+GBN)*GST*2)    // 110592 B
#define EST 132

__global__ void __launch_bounds__(256, 2) gemm_tn(const __half* __restrict__ A,
                                                  const __half* __restrict__ Bm,
                                                  float* __restrict__ C,
                                                  int M, int N, int K, int mode, int batch)
{
    extern __shared__ __align__(16) __half sm[];
    const int tid = threadIdx.x;
    const int w = tid >> 5, l = tid & 31;
    const int wm = w >> 2, wn = w & 3;
    const int m0 = blockIdx.y * GBM, n0 = blockIdx.x * GBN;
    const int NT = K / GBK;
    const int stageH = (GBM + GBN) * GST;

    auto loadStage = [&](int t) {
        __half* sA = sm + (size_t)(t % GNSTG) * stageH;
        __half* sB = sA + GBM * GST;
        const __half* Ag = A + (size_t)m0 * K + t * GBK;
        const __half* Bg = Bm + (size_t)n0 * K + t * GBK;
#pragma unroll
        for (int i = 0; i < 4; i++) {
            int u = tid + i * 256;
            int r = u >> 3, c = (u & 7) * 8;
            cp_async16(sA + r * GST + c, Ag + (size_t)r * K + c);
        }
#pragma unroll
        for (int i = 0; i < 4; i++) {
            int u = tid + i * 256;
            int r = u >> 3, c = (u & 7) * 8;
            cp_async16(sB + r * GST + c, Bg + (size_t)r * K + c);
        }
        cp_commit();
    };

    loadStage(0); loadStage(1);

    float acc[4][4][4];
#pragma unroll
    for (int mi = 0; mi < 4; mi++)
#pragma unroll
        for (int nj = 0; nj < 4; nj++)
#pragma unroll
            for (int e = 0; e < 4; e++) acc[mi][nj][e] = 0.0f;

    const int arow_l = (l & 15);
    const int acoff  = (l >> 4) * 8;
    const int krow   = (l & 7) + ((l >> 4) << 3);
    const int kcol   = ((l >> 3) & 1) * 8;

    for (int t = 0; t < NT; t++) {
        if (t < NT - 1) cp_wait<1>(); else cp_wait<0>();
        __syncthreads();
        if (t + 2 < NT) loadStage(t + 2);

        const __half* sA = sm + (size_t)(t % GNSTG) * stageH;
        const __half* sB = sA + GBM * GST;

#pragma unroll
        for (int dc = 0; dc < 4; dc++) {
            uint32_t a[4][4];
#pragma unroll
            for (int mi = 0; mi < 4; mi++)
                ldsm_x4(smaddr(sA + (wm * 64 + mi * 16 + arow_l) * GST + dc * 16 + acoff),
                        a[mi][0], a[mi][1], a[mi][2], a[mi][3]);
#pragma unroll
            for (int np = 0; np < 2; np++) {
                uint32_t b0, b1, b2, b3;
                ldsm_x4(smaddr(sB + (wn * 32 + np * 16 + krow) * GST + dc * 16 + kcol),
                        b0, b1, b2, b3);
#pragma unroll
                for (int mi = 0; mi < 4; mi++) {
                    mma16816(acc[mi][2 * np],     a[mi], b0, b1);
                    mma16816(acc[mi][2 * np + 1], a[mi], b2, b3);
                }
            }
        }
    }

    if (mode == 0) {
#pragma unroll
        for (int mi = 0; mi < 4; mi++) {
            int row = m0 + wm * 64 + mi * 16 + (l >> 2);
            float* C0 = C + (size_t)row * N + n0 + wn * 32;
            float* C1 = C0 + (size_t)8 * N;
#pragma unroll
            for (int nj = 0; nj < 4; nj++) {
                int col = nj * 8 + (l & 3) * 2;
                *(float2*)(C0 + col) = make_float2(acc[mi][nj][0], acc[mi][nj][1]);
                *(float2*)(C1 + col) = make_float2(acc[mi][nj][2], acc[mi][nj][3]);
            }
        }
        return;
    }

    // fused QKV epilogue (one head per CTA)
    __syncthreads();
    float* sC = (float*)sm;
#pragma unroll
    for (int mi = 0; mi < 4; mi++) {
        int r0 = wm * 64 + mi * 16 + (l >> 2);
#pragma unroll
        for (int nj = 0; nj < 4; nj++) {
            int c0 = wn * 32 + nj * 8 + (l & 3) * 2;
            sC[r0 * EST + c0]           = acc[mi][nj][0];
            sC[r0 * EST + c0 + 1]       = acc[mi][nj][1];
            sC[(r0 + 8) * EST + c0]     = acc[mi][nj][2];
            sC[(r0 + 8) * EST + c0 + 1] = acc[mi][nj][3];
        }
    }
    __syncthreads();

    const int sbase = m0;
    const int bx = blockIdx.x;

    bool do_rope;
    float scl;
    __half* dst;
    if (bx < 16) {
        do_rope = true; scl = QSCL;
        dst = g_Q + ((size_t)(batch * NH + bx) * SEQ) * HD;
    } else if (bx < 20) {
        do_rope = true; scl = 1.0f;
        dst = g_K + ((size_t)(batch * NKV + (bx - 16)) * SEQ) * HD;
    } else {
        do_rope = false; scl = 1.0f;
        dst = g_V + ((size_t)(batch * NKV + (bx - 20)) * SEQ) * HD;
    }

    if (do_rope) {
#pragma unroll
        for (int i = 0; i < 32; i++) {
            int u = tid + i * 256;
            int r = u >> 6, c = u & 63;
            float x1 = sC[r * EST + c], x2 = sC[r * EST + c + 64];
            int s = sbase + r;
            float cs = g_cos[s * 64 + c], sn = g_sin[s * 64 + c];
            dst[(size_t)s * HD + c]      = __float2half((x1 * cs - x2 * sn) * scl);
            dst[(size_t)s * HD + c + 64] = __float2half((x2 * cs + x1 * sn) * scl);
        }
    } else {
#pragma unroll
        for (int i = 0; i < 32; i++) {
            int u = tid + i * 256;
            int r = u >> 6, d2 = (u & 63) * 2;
            int s = sbase + r;
            *(__half2*)(dst + (size_t)s * HD + d2) =
                __floats2half2_rn(sC[r * EST + d2], sC[r * EST + d2 + 1]);
        }
    }
}

// ---------------- FA2 attention: single barrier/iter, 6 KV stages, Q-region reuse ----------
#define TQA 128
#define TKA 64
#define SQL 136
#define KVST (2*TKA*SQL)                 // halfs per stage (K then V)
#define ATTN_SMEM (6*KVST*2)             // 208896 B

__global__ void __launch_bounds__(256) attn_kernel(int batch)
{
    extern __shared__ __align__(16) char smem_raw[];
    __half* stg = (__half*)smem_raw;     // 6 stages; Q parked in stage 5

    const int tid = threadIdx.x;
    const int w = tid >> 5, l = tid & 31;
    const int q0 = blockIdx.x * TQA;
    const int h = blockIdx.y;
    const int b = batch;
    const int kvh = h / (NH / NKV);

    const __half* Qg = g_Q + ((size_t)(b * NH + h) * SEQ + q0) * HD;
    const __half* Kg = g_K + ((size_t)(b * NKV + kvh) * SEQ) * HD;
    const __half* Vg = g_V + ((size_t)(b * NKV + kvh) * SEQ) * HD;
    const int NT2 = SEQ / (2 * TKA);     // 16 pair iterations

    __half* sQ = stg + 5 * KVST;         // Q occupies stage 5 (exactly one stage)

    // group 0: Q
#pragma unroll
    for (int i = 0; i < 8; i++) {
        int u = tid + i * 256;
        int r = u >> 4, c = (u & 15) * 8;
        cp_async16(sQ + r * SQL + c, Qg + r * HD + c);
    }
    cp_commit();

    auto loadKV = [&](int t) {
        int st = t % 6;
        __half* kd = stg + (size_t)st * KVST;
        __half* vd = kd + TKA * SQL;
        const __half* ks = Kg + (size_t)t * TKA * HD;
        const __half* vs = Vg + (size_t)t * TKA * HD;
#pragma unroll
        for (int i = 0; i < 4; i++) {
            int u = tid + i * 256;
            int r = u >> 4, c = (u & 15) * 8;
            cp_async16(kd + r * SQL + c, ks + r * HD + c);
            cp_async16(vd + r * SQL + c, vs + r * HD + c);
        }
        cp_commit();
    };
    loadKV(0); loadKV(1); loadKV(2); loadKV(3);   // groups 1..4 -> stages 0..3

    cp_wait<4>();                // Q complete
    __syncthreads();             // Q visible to all warps

    uint32_t qa[8][4];
    {
        int qrow = w * 16 + (l & 15);
        int coff = (l >> 4) * 8;
#pragma unroll
        for (int dc = 0; dc < 8; dc++)
            ldsm_x4(smaddr(sQ + qrow * SQL + dc * 16 + coff),
                    qa[dc][0], qa[dc][1], qa[dc][2], qa[dc][3]);
    }

    float o[16][4];
#pragma unroll
    for (int j = 0; j < 16; j++)
#pragma unroll
        for (int i = 0; i < 4; i++) o[j][i] = 0.0f;
    float m0 = -1e30f, m1 = -1e30f, l0 = 0.0f, l1 = 0.0f;

    const int krow = (l & 7) + ((l >> 4) << 3);
    const int kcol = ((l >> 3) & 1) * 8;
    const int vrow = (l & 7) + (((l >> 3) & 1) << 3);
    const int vcol = (l >> 4) * 8;

    int ps = 0;                                   // jt % 3: pair -> stages (2ps, 2ps+1)
    for (int jt = 0; jt < NT2; jt++) {
        if (jt < NT2 - 1) cp_wait<2>(); else cp_wait<0>();
        __syncthreads();                          // single barrier per iteration

        const int tA = 2 * jt;
        // prefetch into stages consumed LAST iteration (safe after the barrier);
        // jt==0 targets stage4 (free) and stage5 (Q already in registers)
        if (tA + 4 < 2 * NT2) { loadKV(tA + 4); loadKV(tA + 5); }

        const __half* KtA = stg + (size_t)(2 * ps) * KVST;
        const __half* VtA = KtA + TKA * SQL;
        const __half* KtB = stg + (size_t)(2 * ps + 1) * KVST;
        const __half* VtB = KtB + TKA * SQL;
        ps = (ps == 2) ? 0 : ps + 1;

        float s[16][4];
#pragma unroll
        for (int j = 0; j < 16; j++)
#pragma unroll
            for (int i = 0; i < 4; i++) s[j][i] = 0.0f;
#pragma unroll
        for (int dc = 0; dc < 8; dc++) {
#pragma unroll
            for (int np = 0; np < 4; np++) {
                uint32_t b0, b1, b2, b3;
                ldsm_x4(smaddr(KtA + (np * 16 + krow) * SQL + dc * 16 + kcol),
                        b0, b1, b2, b3);
                mma16816(s[2 * np],     qa[dc], b0, b1);
                mma16816(s[2 * np + 1], qa[dc], b2, b3);
            }
#pragma unroll
            for (int np = 0; np < 4; np++) {
                uint32_t b0, b1, b2, b3;
                ldsm_x4(smaddr(KtB + (np * 16 + krow) * SQL + dc * 16 + kcol),
                        b0, b1, b2, b3);
                mma16816(s[8 + 2 * np],     qa[dc], b0, b1);
                mma16816(s[8 + 2 * np + 1], qa[dc], b2, b3);
            }
        }

        float mx0 = -1e30f, mx1 = -1e30f;
#pragma unroll
        for (int j = 0; j < 16; j++) {
            mx0 = fmaxf(mx0, fmaxf(s[j][0], s[j][1]));
            mx1 = fmaxf(mx1, fmaxf(s[j][2], s[j][3]));
        }
        mx0 = fmaxf(mx0, __shfl_xor_sync(0xffffffffu, mx0, 1));
        mx0 = fmaxf(mx0, __shfl_xor_sync(0xffffffffu, mx0, 2));
        mx1 = fmaxf(mx1, __shfl_xor_sync(0xffffffffu, mx1, 1));
        mx1 = fmaxf(mx1, __shfl_xor_sync(0xffffffffu, mx1, 2));
        float mn0 = fmaxf(m0, mx0), mn1 = fmaxf(m1, mx1);

        float f0 = 1.0f, f1 = 1.0f;
        bool upd = (mn0 > m0) || (mn1 > m1);
        if (__any_sync(0xffffffffu, upd)) {
            f0 = exp2f(m0 - mn0); f1 = exp2f(m1 - mn1);
            m0 = mn0; m1 = mn1;
#pragma unroll
            for (int j = 0; j < 16; j++) {
                o[j][0] *= f0; o[j][1] *= f0;
                o[j][2] *= f1; o[j][3] *= f1;
            }
        }

        float sum0 = 0.0f, sum1 = 0.0f;
#pragma unroll
        for (int j = 0; j < 16; j++) {
            s[j][0] = exp2f(s[j][0] - mn0);
            s[j][1] = exp2f(s[j][1] - mn0);
            s[j][2] = exp2f(s[j][2] - mn1);
            s[j][3] = exp2f(s[j][3] - mn1);
            sum0 += s[j][0] + s[j][1];
            sum1 += s[j][2] + s[j][3];
        }
        sum0 += __shfl_xor_sync(0xffffffffu, sum0, 1);
        sum0 += __shfl_xor_sync(0xffffffffu, sum0, 2);
        sum1 += __shfl_xor_sync(0xffffffffu, sum1, 1);
        sum1 += __shfl_xor_sync(0xffffffffu, sum1, 2);
        l0 = l0 * f0 + sum0;
        l1 = l1 * f1 + sum1;

#pragma unroll
        for (int t = 0; t < 4; t++) {
            uint32_t pa[4];
            pa[0] = h2pack(s[2 * t][0],     s[2 * t][1]);
            pa[1] = h2pack(s[2 * t][2],     s[2 * t][3]);
            pa[2] = h2pack(s[2 * t + 1][0], s[2 * t + 1][1]);
            pa[3] = h2pack(s[2 * t + 1][2], s[2 * t + 1][3]);
#pragma unroll
            for (int npp = 0; npp < 8; npp++) {
                uint32_t b0, b1, b2, b3;
                ldsm_x4_t(smaddr(VtA + (t * 16 + vrow) * SQL + npp * 16 + vcol),
                          b0, b1, b2, b3);
                mma16816(o[2 * npp],     pa, b0, b1);
                mma16816(o[2 * npp + 1], pa, b2, b3);
            }
        }
#pragma unroll
        for (int t = 0; t < 4; t++) {
            uint32_t pa[4];
            pa[0] = h2pack(s[8 + 2 * t][0],     s[8 + 2 * t][1]);
            pa[1] = h2pack(s[8 + 2 * t][2],     s[8 + 2 * t][3]);
            pa[2] = h2pack(s[8 + 2 * t + 1][0], s[8 + 2 * t + 1][1]);
            pa[3] = h2pack(s[8 + 2 * t + 1][2], s[8 + 2 * t + 1][3]);
#pragma unroll
            for (int npp = 0; npp < 8; npp++) {
                uint32_t b0, b1, b2, b3;
                ldsm_x4_t(smaddr(VtB + (t * 16 + vrow) * SQL + npp * 16 + vcol),
                          b0, b1, b2, b3);
                mma16816(o[2 * npp],     pa, b0, b1);
                mma16816(o[2 * npp + 1], pa, b2, b3);
            }
        }
    }

    float inv0 = 1.0f / l0, inv1 = 1.0f / l1;
    int grow = b * SEQ + q0 + w * 16 + (l >> 2);
    __half* O0 = g_attn + (size_t)grow * (NH * HD) + h * HD;
    __half* O1 = O0 + (size_t)8 * (NH * HD);
#pragma unroll
    for (int j = 0; j < 16; j++) {
        int col = j * 8 + 2 * (l & 3);
        *(__half2*)(O0 + col) = __floats2half2_rn(o[j][0] * inv0, o[j][1] * inv0);
        *(__half2*)(O1 + col) = __floats2half2_rn(o[j][2] * inv1, o[j][3] * inv1);
    }
}

// ---------------- launch: split conversions + two per-batch chains ----------------
extern "C" void kernel_launch(void* const* d_in, const int* in_sizes, int n_in,
                              void* d_out, int out_size)
{
    const float* hidden = (const float*)d_in[0];
    const float* Wq = (const float*)d_in[1];
    const float* Wk = (const float*)d_in[2];
    const float* Wv = (const float*)d_in[3];
    const float* Wo = (const float*)d_in[4];
    float* out = (float*)d_out;

    static cudaStream_t s_aux = nullptr;
    static cudaEvent_t  s_evA = nullptr, s_evW = nullptr, s_evB = nullptr;
    if (s_aux == nullptr) {
        cudaStreamCreateWithFlags(&s_aux, cudaStreamNonBlocking);
        cudaEventCreateWithFlags(&s_evA, cudaEventDisableTiming);
        cudaEventCreateWithFlags(&s_evW, cudaEventDisableTiming);
        cudaEventCreateWithFlags(&s_evB, cudaEventDisableTiming);
    }

    cudaFuncSetAttribute(attn_kernel, cudaFuncAttributeMaxDynamicSharedMemorySize, ATTN_SMEM);
    cudaFuncSetAttribute(gemm_tn, cudaFuncAttributeMaxDynamicSharedMemorySize, GEMM_SMEM);

    __half *p_hX, *p_Wqkv, *p_Wo, *p_attn;
    cudaGetSymbolAddress((void**)&p_hX,   g_hX);
    cudaGetSymbolAddress((void**)&p_Wqkv, g_Wqkv);
    cudaGetSymbolAddress((void**)&p_Wo,   g_Wo);
    cudaGetSymbolAddress((void**)&p_attn, g_attn);

    const int T = 256;

    // convA (critical for chain b0): hX[b0] + Wqkv + rope table   [main]
    convA<<<CONVA_BLOCKS, T>>>((const float4*)hidden, (const float4*)Wq,
                               (const float4*)Wk, (const float4*)Wv);
    cudaEventRecord(s_evA, 0);
    cudaStreamWaitEvent(s_aux, s_evA, 0);

    // convB: hX[b1] + Wo   [aux, overlaps chain b0's QKV gemm]
    convB<<<CONVB_BLOCKS, T, 0, s_aux>>>(
        (const float4*)(hidden + (size_t)SEQ*HID), (const float4*)Wo);
    cudaEventRecord(s_evW, s_aux);

    // chain b=0 on main stream
    gemm_tn<<<dim3(NQKV/GBN, SEQ/GBM), T, GEMM_SMEM>>>(
        p_hX, p_Wqkv, (float*)nullptr, SEQ, NQKV, HID, 1, 0);
    attn_kernel<<<dim3(SEQ/TQA, NH), T, ATTN_SMEM>>>(0);
    cudaStreamWaitEvent(0, s_evW, 0);          // Wo converted (always ready by now)
    gemm_tn<<<dim3(HID/GBN, SEQ/GBM), T, GEMM_SMEM>>>(
        p_attn, p_Wo, out, SEQ, HID, NH*HD, 0, 0);

    // chain b=1 on aux stream
    gemm_tn<<<dim3(NQKV/GBN, SEQ/GBM), T, GEMM_SMEM, s_aux>>>(
        p_hX + (size_t)SEQ*HID, p_Wqkv, (float*)nullptr, SEQ, NQKV, HID, 1, 1);
    attn_kernel<<<dim3(SEQ/TQA, NH), T, ATTN_SMEM, s_aux>>>(1);
    gemm_tn<<<dim3(HID/GBN, SEQ/GBM), T, GEMM_SMEM, s_aux>>>(
        p_attn + (size_t)SEQ*NH*HD, p_Wo, out + (size_t)SEQ*HID, SEQ, HID, NH*HD, 0, 1);

    // join
    cudaEventRecord(s_evB, s_aux);
    cudaStreamWaitEvent(0, s_evB, 0);
}

// round 17
// speedup vs baseline: 1.0088x; 1.0004x over previous
#include <cuda_runtime.h>
#include <cuda_fp16.h>
#include <math.h>
#include <stdint.h>
#include <cstdint>

#define NH   16
#define NKV  4
#define HD   128
#define BB   2
#define SEQ  2048
#define HID  2048
#define MROWS (BB*SEQ)
#define NQKV 3072

// scale folded into Q: (1/sqrt(128)) * log2(e)
#define QSCL 0.1275174337f

// ---------------- device scratch ----------------
__device__ __half g_hX  [MROWS*HID];
__device__ __half g_Wqkv[NQKV*HID];        // Wq | Wk | Wv rows
__device__ __half g_Wo  [HID*NH*HD];
__device__ __half g_Q   [BB*NH*SEQ*HD];
__device__ __half g_K   [BB*NKV*SEQ*HD];
__device__ __half g_V   [BB*NKV*SEQ*HD];
__device__ __half g_attn[MROWS*NH*HD];
__device__ float  g_cos[SEQ*64];
__device__ float  g_sin[SEQ*64];

// ---------------- cp.async helpers ----------------
__device__ __forceinline__ void cp_async16(void* smem, const void* gmem)
{
    unsigned s = (unsigned)__cvta_generic_to_shared(smem);
    asm volatile("cp.async.cg.shared.global [%0], [%1], 16;\n" :: "r"(s), "l"(gmem));
}
__device__ __forceinline__ void cp_commit() { asm volatile("cp.async.commit_group;\n"); }
template<int N> __device__ __forceinline__ void cp_wait()
{
    asm volatile("cp.async.wait_group %0;\n" :: "n"(N));
}

// ---------------- mma / ldmatrix primitives ----------------
__device__ __forceinline__ uint32_t smaddr(const void* p)
{
    return (uint32_t)__cvta_generic_to_shared(p);
}
__device__ __forceinline__ void ldsm_x4(uint32_t a, uint32_t& r0, uint32_t& r1,
                                        uint32_t& r2, uint32_t& r3)
{
    asm volatile("ldmatrix.sync.aligned.m8n8.x4.shared.b16 {%0,%1,%2,%3}, [%4];"
                 : "=r"(r0), "=r"(r1), "=r"(r2), "=r"(r3) : "r"(a));
}
__device__ __forceinline__ void ldsm_x4_t(uint32_t a, uint32_t& r0, uint32_t& r1,
                                          uint32_t& r2, uint32_t& r3)
{
    asm volatile("ldmatrix.sync.aligned.m8n8.x4.trans.shared.b16 {%0,%1,%2,%3}, [%4];"
                 : "=r"(r0), "=r"(r1), "=r"(r2), "=r"(r3) : "r"(a));
}
__device__ __forceinline__ void mma16816(float* c, const uint32_t* a, uint32_t b0, uint32_t b1)
{
    asm volatile("mma.sync.aligned.m16n8k16.row.col.f32.f16.f16.f32 "
                 "{%0,%1,%2,%3}, {%4,%5,%6,%7}, {%8,%9}, {%0,%1,%2,%3};"
                 : "+f"(c[0]), "+f"(c[1]), "+f"(c[2]), "+f"(c[3])
                 : "r"(a[0]), "r"(a[1]), "r"(a[2]), "r"(a[3]), "r"(b0), "r"(b1));
}
__device__ __forceinline__ uint32_t h2pack(float x, float y)
{
    __half2 h = __floats2half2_rn(x, y);
    return *(uint32_t*)&h;
}

// ---------------- split conversions ----------------
#define CA0 1048576L
#define CA1 (CA0 + 1048576L)
#define CA2 (CA1 + 524288L)
#define CA3 (CA2 + 524288L)
#define TAB_BLOCKS 512
#define CONVA_BLOCKS (CA3 / 256 + TAB_BLOCKS)

__global__ void convA(const float4* __restrict__ hX, const float4* __restrict__ Wq,
                      const float4* __restrict__ Wk, const float4* __restrict__ Wv)
{
    long i = (long)blockIdx.x * 256 + threadIdx.x;
    if (i >= CA3) {
        long t = i - CA3;
        int s = (int)(t / 64), k = (int)(t % 64);
        double inv = pow(10000.0, -(double)k / 64.0);
        double ang = (double)s * inv;
        double sn, cs;
        sincos(ang, &sn, &cs);
        g_cos[t] = (float)cs;
        g_sin[t] = (float)sn;
        return;
    }
    const float4* src; __half* dst; long off;
    if (i < CA0)      { src = hX; dst = g_hX;   off = i; }
    else if (i < CA1) { src = Wq; dst = g_Wqkv; off = i - CA0; }
    else if (i < CA2) { src = Wk; dst = g_Wqkv + (size_t)2048*HID; off = i - CA1; }
    else              { src = Wv; dst = g_Wqkv + (size_t)2560*HID; off = i - CA2; }
    float4 v = src[off];
    __half2* d = (__half2*)(dst + off * 4);
    d[0] = __floats2half2_rn(v.x, v.y);
    d[1] = __floats2half2_rn(v.z, v.w);
}

#define CB0 1048576L
#define CB1 (CB0 + 1048576L)
#define CONVB_BLOCKS (CB1 / 256)

__global__ void convB(const float4* __restrict__ hXb1, const float4* __restrict__ Wo)
{
    long i = (long)blockIdx.x * 256 + threadIdx.x;
    const float4* src; __half* dst; long off;
    if (i < CB0) { src = hXb1; dst = g_hX + (size_t)SEQ*HID; off = i; }
    else         { src = Wo;   dst = g_Wo;                   off = i - CB0; }
    float4 v = src[off];
    __half2* d = (__half2*)(dst + off * 4);
    d[0] = __floats2half2_rn(v.x, v.y);
    d[1] = __floats2half2_rn(v.z, v.w);
}

// ======== Raw-mma TN GEMM, CTA 128x128, warp tile 64x32, 2 CTAs/SM ========
#define GBM 128
#define GBN 128
#define GBK 64
#define GST 72
#define GNSTG 3
#define GEMM_SMEM (GNSTG*(GBM+GBN)*GST*2)    // 110592 B
#define EST 132

__global__ void __launch_bounds__(256, 2) gemm_tn(const __half* __restrict__ A,
                                                  const __half* __restrict__ Bm,
                                                  float* __restrict__ C,
                                                  int M, int N, int K, int mode, int batch)
{
    extern __shared__ __align__(16) __half sm[];
    const int tid = threadIdx.x;
    const int w = tid >> 5, l = tid & 31;
    const int wm = w >> 2, wn = w & 3;
    const int m0 = blockIdx.y * GBM, n0 = blockIdx.x * GBN;
    const int NT = K / GBK;
    const int stageH = (GBM + GBN) * GST;

    auto loadStage = [&](int t) {
        __half* sA = sm + (size_t)(t % GNSTG) * stageH;
        __half* sB = sA + GBM * GST;
        const __half* Ag = A + (size_t)m0 * K + t * GBK;
        const __half* Bg = Bm + (size_t)n0 * K + t * GBK;
#pragma unroll
        for (int i = 0; i < 4; i++) {
            int u = tid + i * 256;
            int r = u >> 3, c = (u & 7) * 8;
            cp_async16(sA + r * GST + c, Ag + (size_t)r * K + c);
        }
#pragma unroll
        for (int i = 0; i < 4; i++) {
            int u = tid + i * 256;
            int r = u >> 3, c = (u & 7) * 8;
            cp_async16(sB + r * GST + c, Bg + (size_t)r * K + c);
        }
        cp_commit();
    };

    loadStage(0); loadStage(1);

    float acc[4][4][4];
#pragma unroll
    for (int mi = 0; mi < 4; mi++)
#pragma unroll
        for (int nj = 0; nj < 4; nj++)
#pragma unroll
            for (int e = 0; e < 4; e++) acc[mi][nj][e] = 0.0f;

    const int arow_l = (l & 15);
    const int acoff  = (l >> 4) * 8;
    const int krow   = (l & 7) + ((l >> 4) << 3);
    const int kcol   = ((l >> 3) & 1) * 8;

    for (int t = 0; t < NT; t++) {
        if (t < NT - 1) cp_wait<1>(); else cp_wait<0>();
        __syncthreads();
        if (t + 2 < NT) loadStage(t + 2);

        const __half* sA = sm + (size_t)(t % GNSTG) * stageH;
        const __half* sB = sA + GBM * GST;

#pragma unroll
        for (int dc = 0; dc < 4; dc++) {
            uint32_t a[4][4];
#pragma unroll
            for (int mi = 0; mi < 4; mi++)
                ldsm_x4(smaddr(sA + (wm * 64 + mi * 16 + arow_l) * GST + dc * 16 + acoff),
                        a[mi][0], a[mi][1], a[mi][2], a[mi][3]);
#pragma unroll
            for (int np = 0; np < 2; np++) {
                uint32_t b0, b1, b2, b3;
                ldsm_x4(smaddr(sB + (wn * 32 + np * 16 + krow) * GST + dc * 16 + kcol),
                        b0, b1, b2, b3);
#pragma unroll
                for (int mi = 0; mi < 4; mi++) {
                    mma16816(acc[mi][2 * np],     a[mi], b0, b1);
                    mma16816(acc[mi][2 * np + 1], a[mi], b2, b3);
                }
            }
        }
    }

    if (mode == 0) {
#pragma unroll
        for (int mi = 0; mi < 4; mi++) {
            int row = m0 + wm * 64 + mi * 16 + (l >> 2);
            float* C0 = C + (size_t)row * N + n0 + wn * 32;
            float* C1 = C0 + (size_t)8 * N;
#pragma unroll
            for (int nj = 0; nj < 4; nj++) {
                int col = nj * 8 + (l & 3) * 2;
                *(float2*)(C0 + col) = make_float2(acc[mi][nj][0], acc[mi][nj][1]);
                *(float2*)(C1 + col) = make_float2(acc[mi][nj][2], acc[mi][nj][3]);
            }
        }
        return;
    }

    // fused QKV epilogue (one head per CTA)
    __syncthreads();
    float* sC = (float*)sm;
#pragma unroll
    for (int mi = 0; mi < 4; mi++) {
        int r0 = wm * 64 + mi * 16 + (l >> 2);
#pragma unroll
        for (int nj = 0; nj < 4; nj++) {
            int c0 = wn * 32 + nj * 8 + (l & 3) * 2;
            sC[r0 * EST + c0]           = acc[mi][nj][0];
            sC[r0 * EST + c0 + 1]       = acc[mi][nj][1];
            sC[(r0 + 8) * EST + c0]     = acc[mi][nj][2];
            sC[(r0 + 8) * EST + c0 + 1] = acc[mi][nj][3];
        }
    }
    __syncthreads();

    const int sbase = m0;
    const int bx = blockIdx.x;

    bool do_rope;
    float scl;
    __half* dst;
    if (bx < 16) {
        do_rope = true; scl = QSCL;
        dst = g_Q + ((size_t)(batch * NH + bx) * SEQ) * HD;
    } else if (bx < 20) {
        do_rope = true; scl = 1.0f;
        dst = g_K + ((size_t)(batch * NKV + (bx - 16)) * SEQ) * HD;
    } else {
        do_rope = false; scl = 1.0f;
        dst = g_V + ((size_t)(batch * NKV + (bx - 20)) * SEQ) * HD;
    }

    if (do_rope) {
#pragma unroll
        for (int i = 0; i < 32; i++) {
            int u = tid + i * 256;
            int r = u >> 6, c = u & 63;
            float x1 = sC[r * EST + c], x2 = sC[r * EST + c + 64];
            int s = sbase + r;
            float cs = g_cos[s * 64 + c], sn = g_sin[s * 64 + c];
            dst[(size_t)s * HD + c]      = __float2half((x1 * cs - x2 * sn) * scl);
            dst[(size_t)s * HD + c + 64] = __float2half((x2 * cs + x1 * sn) * scl);
        }
    } else {
#pragma unroll
        for (int i = 0; i < 32; i++) {
            int u = tid + i * 256;
            int r = u >> 6, d2 = (u & 63) * 2;
            int s = sbase + r;
            *(__half2*)(dst + (size_t)s * HD + d2) =
                __floats2half2_rn(sC[r * EST + d2], sC[r * EST + d2 + 1]);
        }
    }
}

// ---------------- FA2 attention: running-max softmax (proven), single barrier,
// 6 KV stages with Q-region reuse, deferred l-reduction ----------
#define TQA 128
#define TKA 64
#define SQL 136
#define KVST (2*TKA*SQL)                 // halfs per stage (K then V)
#define ATTN_SMEM (6*KVST*2)             // 208896 B

__global__ void __launch_bounds__(256) attn_kernel(int batch)
{
    extern __shared__ __align__(16) char smem_raw[];
    __half* stg = (__half*)smem_raw;     // 6 stages; Q parked in stage 5

    const int tid = threadIdx.x;
    const int w = tid >> 5, l = tid & 31;
    const int q0 = blockIdx.x * TQA;
    const int h = blockIdx.y;
    const int b = batch;
    const int kvh = h / (NH / NKV);

    const __half* Qg = g_Q + ((size_t)(b * NH + h) * SEQ + q0) * HD;
    const __half* Kg = g_K + ((size_t)(b * NKV + kvh) * SEQ) * HD;
    const __half* Vg = g_V + ((size_t)(b * NKV + kvh) * SEQ) * HD;
    const int NT2 = SEQ / (2 * TKA);     // 16 pair iterations

    __half* sQ = stg + 5 * KVST;         // Q occupies stage 5

    // group 0: Q
#pragma unroll
    for (int i = 0; i < 8; i++) {
        int u = tid + i * 256;
        int r = u >> 4, c = (u & 15) * 8;
        cp_async16(sQ + r * SQL + c, Qg + r * HD + c);
    }
    cp_commit();

    auto loadKV = [&](int t) {
        int st = t % 6;
        __half* kd = stg + (size_t)st * KVST;
        __half* vd = kd + TKA * SQL;
        const __half* ks = Kg + (size_t)t * TKA * HD;
        const __half* vs = Vg + (size_t)t * TKA * HD;
#pragma unroll
        for (int i = 0; i < 4; i++) {
            int u = tid + i * 256;
            int r = u >> 4, c = (u & 15) * 8;
            cp_async16(kd + r * SQL + c, ks + r * HD + c);
            cp_async16(vd + r * SQL + c, vs + r * HD + c);
        }
        cp_commit();
    };
    loadKV(0); loadKV(1); loadKV(2); loadKV(3);

    cp_wait<4>();                // Q complete
    __syncthreads();

    uint32_t qa[8][4];
    {
        int qrow = w * 16 + (l & 15);
        int coff = (l >> 4) * 8;
#pragma unroll
        for (int dc = 0; dc < 8; dc++)
            ldsm_x4(smaddr(sQ + qrow * SQL + dc * 16 + coff),
                    qa[dc][0], qa[dc][1], qa[dc][2], qa[dc][3]);
    }

    float o[16][4];
#pragma unroll
    for (int j = 0; j < 16; j++)
#pragma unroll
        for (int i = 0; i < 4; i++) o[j][i] = 0.0f;
    float m0 = -1e30f, m1 = -1e30f, l0 = 0.0f, l1 = 0.0f;   // l: per-thread partial

    const int krow = (l & 7) + ((l >> 4) << 3);
    const int kcol = ((l >> 3) & 1) * 8;
    const int vrow = (l & 7) + (((l >> 3) & 1) << 3);
    const int vcol = (l >> 4) * 8;

    int ps = 0;
    for (int jt = 0; jt < NT2; jt++) {
        if (jt < NT2 - 1) cp_wait<2>(); else cp_wait<0>();
        __syncthreads();

        const int tA = 2 * jt;
        if (tA + 4 < 2 * NT2) { loadKV(tA + 4); loadKV(tA + 5); }

        const __half* KtA = stg + (size_t)(2 * ps) * KVST;
        const __half* VtA = KtA + TKA * SQL;
        const __half* KtB = stg + (size_t)(2 * ps + 1) * KVST;
        const __half* VtB = KtB + TKA * SQL;
        ps = (ps == 2) ? 0 : ps + 1;

        float s[16][4];
#pragma unroll
        for (int j = 0; j < 16; j++)
#pragma unroll
            for (int i = 0; i < 4; i++) s[j][i] = 0.0f;
#pragma unroll
        for (int dc = 0; dc < 8; dc++) {
#pragma unroll
            for (int np = 0; np < 4; np++) {
                uint32_t b0, b1, b2, b3;
                ldsm_x4(smaddr(KtA + (np * 16 + krow) * SQL + dc * 16 + kcol),
                        b0, b1, b2, b3);
                mma16816(s[2 * np],     qa[dc], b0, b1);
                mma16816(s[2 * np + 1], qa[dc], b2, b3);
            }
#pragma unroll
            for (int np = 0; np < 4; np++) {
                uint32_t b0, b1, b2, b3;
                ldsm_x4(smaddr(KtB + (np * 16 + krow) * SQL + dc * 16 + kcol),
                        b0, b1, b2, b3);
                mma16816(s[8 + 2 * np],     qa[dc], b0, b1);
                mma16816(s[8 + 2 * np + 1], qa[dc], b2, b3);
            }
        }

        // running-max softmax (max-reduction across row's 4 threads; l deferred)
        float mx0 = -1e30f, mx1 = -1e30f;
#pragma unroll
        for (int j = 0; j < 16; j++) {
            mx0 = fmaxf(mx0, fmaxf(s[j][0], s[j][1]));
            mx1 = fmaxf(mx1, fmaxf(s[j][2], s[j][3]));
        }
        mx0 = fmaxf(mx0, __shfl_xor_sync(0xffffffffu, mx0, 1));
        mx0 = fmaxf(mx0, __shfl_xor_sync(0xffffffffu, mx0, 2));
        mx1 = fmaxf(mx1, __shfl_xor_sync(0xffffffffu, mx1, 1));
        mx1 = fmaxf(mx1, __shfl_xor_sync(0xffffffffu, mx1, 2));
        float mn0 = fmaxf(m0, mx0), mn1 = fmaxf(m1, mx1);

        float f0 = 1.0f, f1 = 1.0f;
        bool upd = (mn0 > m0) || (mn1 > m1);
        if (__any_sync(0xffffffffu, upd)) {
            f0 = exp2f(m0 - mn0); f1 = exp2f(m1 - mn1);
            m0 = mn0; m1 = mn1;
#pragma unroll
            for (int j = 0; j < 16; j++) {
                o[j][0] *= f0; o[j][1] *= f0;
                o[j][2] *= f1; o[j][3] *= f1;
            }
        }

        float sum0 = 0.0f, sum1 = 0.0f;
#pragma unroll
        for (int j = 0; j < 16; j++) {
            s[j][0] = exp2f(s[j][0] - mn0);
            s[j][1] = exp2f(s[j][1] - mn0);
            s[j][2] = exp2f(s[j][2] - mn1);
            s[j][3] = exp2f(s[j][3] - mn1);
            sum0 += s[j][0] + s[j][1];
            sum1 += s[j][2] + s[j][3];
        }
        // per-thread partial l only; cross-thread combine deferred to epilogue
        l0 = l0 * f0 + sum0;
        l1 = l1 * f1 + sum1;

#pragma unroll
        for (int t = 0; t < 4; t++) {
            uint32_t pa[4];
            pa[0] = h2pack(s[2 * t][0],     s[2 * t][1]);
            pa[1] = h2pack(s[2 * t][2],     s[2 * t][3]);
            pa[2] = h2pack(s[2 * t + 1][0], s[2 * t + 1][1]);
            pa[3] = h2pack(s[2 * t + 1][2], s[2 * t + 1][3]);
#pragma unroll
            for (int npp = 0; npp < 8; npp++) {
                uint32_t b0, b1, b2, b3;
                ldsm_x4_t(smaddr(VtA + (t * 16 + vrow) * SQL + npp * 16 + vcol),
                          b0, b1, b2, b3);
                mma16816(o[2 * npp],     pa, b0, b1);
                mma16816(o[2 * npp + 1], pa, b2, b3);
            }
        }
#pragma unroll
        for (int t = 0; t < 4; t++) {
            uint32_t pa[4];
            pa[0] = h2pack(s[8 + 2 * t][0],     s[8 + 2 * t][1]);
            pa[1] = h2pack(s[8 + 2 * t][2],     s[8 + 2 * t][3]);
            pa[2] = h2pack(s[8 + 2 * t + 1][0], s[8 + 2 * t + 1][1]);
            pa[3] = h2pack(s[8 + 2 * t + 1][2], s[8 + 2 * t + 1][3]);
#pragma unroll
            for (int npp = 0; npp < 8; npp++) {
                uint32_t b0, b1, b2, b3;
                ldsm_x4_t(smaddr(VtB + (t * 16 + vrow) * SQL + npp * 16 + vcol),
                          b0, b1, b2, b3);
                mma16816(o[2 * npp],     pa, b0, b1);
                mma16816(o[2 * npp + 1], pa, b2, b3);
            }
        }
    }

    // epilogue: combine per-thread partial l across the row's 4 threads (once)
    l0 += __shfl_xor_sync(0xffffffffu, l0, 1);
    l0 += __shfl_xor_sync(0xffffffffu, l0, 2);
    l1 += __shfl_xor_sync(0xffffffffu, l1, 1);
    l1 += __shfl_xor_sync(0xffffffffu, l1, 2);

    float inv0 = 1.0f / l0, inv1 = 1.0f / l1;
    int grow = b * SEQ + q0 + w * 16 + (l >> 2);
    __half* O0 = g_attn + (size_t)grow * (NH * HD) + h * HD;
    __half* O1 = O0 + (size_t)8 * (NH * HD);
#pragma unroll
    for (int j = 0; j < 16; j++) {
        int col = j * 8 + 2 * (l & 3);
        *(__half2*)(O0 + col) = __floats2half2_rn(o[j][0] * inv0, o[j][1] * inv0);
        *(__half2*)(O1 + col) = __floats2half2_rn(o[j][2] * inv1, o[j][3] * inv1);
    }
}

// ---------------- launch: split conversions + two per-batch chains ----------------
extern "C" void kernel_launch(void* const* d_in, const int* in_sizes, int n_in,
                              void* d_out, int out_size)
{
    const float* hidden = (const float*)d_in[0];
    const float* Wq = (const float*)d_in[1];
    const float* Wk = (const float*)d_in[2];
    const float* Wv = (const float*)d_in[3];
    const float* Wo = (const float*)d_in[4];
    float* out = (float*)d_out;

    static cudaStream_t s_aux = nullptr;
    static cudaEvent_t  s_evA = nullptr, s_evW = nullptr, s_evB = nullptr;
    if (s_aux == nullptr) {
        cudaStreamCreateWithFlags(&s_aux, cudaStreamNonBlocking);
        cudaEventCreateWithFlags(&s_evA, cudaEventDisableTiming);
        cudaEventCreateWithFlags(&s_evW, cudaEventDisableTiming);
        cudaEventCreateWithFlags(&s_evB, cudaEventDisableTiming);
    }

    cudaFuncSetAttribute(attn_kernel, cudaFuncAttributeMaxDynamicSharedMemorySize, ATTN_SMEM);
    cudaFuncSetAttribute(gemm_tn, cudaFuncAttributeMaxDynamicSharedMemorySize, GEMM_SMEM);

    __half *p_hX, *p_Wqkv, *p_Wo, *p_attn;
    cudaGetSymbolAddress((void**)&p_hX,   g_hX);
    cudaGetSymbolAddress((void**)&p_Wqkv, g_Wqkv);
    cudaGetSymbolAddress((void**)&p_Wo,   g_Wo);
    cudaGetSymbolAddress((void**)&p_attn, g_attn);

    const int T = 256;

    // convA (critical for chain b0): hX[b0] + Wqkv + rope table   [main]
    convA<<<CONVA_BLOCKS, T>>>((const float4*)hidden, (const float4*)Wq,
                               (const float4*)Wk, (const float4*)Wv);
    cudaEventRecord(s_evA, 0);
    cudaStreamWaitEvent(s_aux, s_evA, 0);

    // convB: hX[b1] + Wo   [aux, overlaps chain b0's QKV gemm]
    convB<<<CONVB_BLOCKS, T, 0, s_aux>>>(
        (const float4*)(hidden + (size_t)SEQ*HID), (const float4*)Wo);
    cudaEventRecord(s_evW, s_aux);

    // chain b=0 on main stream
    gemm_tn<<<dim3(NQKV/GBN, SEQ/GBM), T, GEMM_SMEM>>>(
        p_hX, p_Wqkv, (float*)nullptr, SEQ, NQKV, HID, 1, 0);
    attn_kernel<<<dim3(SEQ/TQA, NH), T, ATTN_SMEM>>>(0);
    cudaStreamWaitEvent(0, s_evW, 0);
    gemm_tn<<<dim3(HID/GBN, SEQ/GBM), T, GEMM_SMEM>>>(
        p_attn, p_Wo, out, SEQ, HID, NH*HD, 0, 0);

    // chain b=1 on aux stream
    gemm_tn<<<dim3(NQKV/GBN, SEQ/GBM), T, GEMM_SMEM, s_aux>>>(
        p_hX + (size_t)SEQ*HID, p_Wqkv, (float*)nullptr, SEQ, NQKV, HID, 1, 1);
    attn_kernel<<<dim3(SEQ/TQA, NH), T, ATTN_SMEM, s_aux>>>(1);
    gemm_tn<<<dim3(HID/GBN, SEQ/GBM), T, GEMM_SMEM, s_aux>>>(
        p_attn + (size_t)SEQ*NH*HD, p_Wo, out + (size_t)SEQ*HID, SEQ, HID, NH*HD, 0, 1);

    // join
    cudaEventRecord(s_evB, s_aux);
    cudaStreamWaitEvent(0, s_evB, 0);
}